// round 1
// baseline (speedup 1.0000x reference)
#include <cuda_runtime.h>
#include <stdint.h>

// EdgeFeaturizer: per-row 12 smallest of an 8192x8192 uniform distance matrix,
// then edge_index [n*k,2] + Gaussian RBF features [n*k,50], concatenated into
// one float32 output buffer (edge_index first, as floats).

#define N_ATOMS   8192
#define KNBR      12
#define NBINS     50
#define CAP       2048          // candidate buffer per row (mean ~82 at t=0.01)
#define THREADS   256

__global__ __launch_bounds__(THREADS)
void edge_featurizer_kernel(const float* __restrict__ dm, float* __restrict__ out)
{
    __shared__ unsigned long long cand[CAP];
    __shared__ int   s_count;
    __shared__ float s_tc[NBINS];        // exp(-12.5 * c_j^2)
    __shared__ float s_d[KNBR];
    __shared__ int   s_i[KNBR];
    __shared__ float s_feat[KNBR * NBINS];

    const int row = blockIdx.x;
    const int tid = threadIdx.x;
    const float4* __restrict__ rp =
        reinterpret_cast<const float4*>(dm + (size_t)row * N_ATOMS);

    // Constant RBF table (centers c_j = j/49), tiny MUFU cost per block.
    if (tid < NBINS) {
        float c = (float)tid * (1.0f / 49.0f);
        s_tc[tid] = __expf(-12.5f * c * c);
    }
    if (tid == 0) s_count = 0;
    __syncthreads();

    // ---- Phase 1: exact threshold-compaction with fallback ----
    float t = 0.01f;   // P(count<12) ~ 1e-22, P(count>CAP) ~ 0 for U[0,1) rows
    int   c;
    for (;;) {
        #pragma unroll
        for (int ii = 0; ii < (N_ATOMS / 4) / THREADS; ii++) {
            int i = tid + ii * THREADS;
            float4 v = __ldcs(rp + i);           // streaming: read-once data
            unsigned base = 4u * (unsigned)i;
            if (v.x < t) { int p = atomicAdd(&s_count, 1); if (p < CAP)
                cand[p] = (((unsigned long long)__float_as_uint(v.x)) << 32) | (base + 0u); }
            if (v.y < t) { int p = atomicAdd(&s_count, 1); if (p < CAP)
                cand[p] = (((unsigned long long)__float_as_uint(v.y)) << 32) | (base + 1u); }
            if (v.z < t) { int p = atomicAdd(&s_count, 1); if (p < CAP)
                cand[p] = (((unsigned long long)__float_as_uint(v.z)) << 32) | (base + 2u); }
            if (v.w < t) { int p = atomicAdd(&s_count, 1); if (p < CAP)
                cand[p] = (((unsigned long long)__float_as_uint(v.w)) << 32) | (base + 3u); }
        }
        __syncthreads();
        c = s_count;
        __syncthreads();                 // everyone has read c before reset
        if (c >= KNBR && c <= CAP) break;
        t = (c < KNBR) ? t * 8.0f : t * 0.125f;
        if (tid == 0) s_count = 0;
        __syncthreads();
    }

    // ---- Phase 2: warp 0 extracts the 12 smallest keys (value, then index) ----
    if (tid < 32) {
        for (int k = 0; k < KNBR; k++) {
            unsigned long long best = ~0ull;
            for (int i = tid; i < c; i += 32) {
                unsigned long long v = cand[i];
                if (v < best) best = v;
            }
            #pragma unroll
            for (int off = 16; off > 0; off >>= 1) {
                unsigned long long o = __shfl_down_sync(0xffffffffu, best, off);
                if (o < best) best = o;
            }
            best = __shfl_sync(0xffffffffu, best, 0);
            for (int i = tid; i < c; i += 32)        // keys unique (idx in key)
                if (cand[i] == best) cand[i] = ~0ull;
            if (tid == 0) {
                s_d[k] = __uint_as_float((unsigned)(best >> 32));
                s_i[k] = (int)(best & 0xffffffffu);
            }
        }
    }
    __syncthreads();

    // ---- Phase 3: features via geometric recurrence (2 MUFU per edge) ----
    // exp(-12.5 (d - c_j)^2) = exp(-12.5 d^2) * r^j * exp(-12.5 c_j^2),
    // r = exp(25 * d / 49).
    if (tid < KNBR) {
        float d  = s_d[tid];
        float e0 = __expf(-12.5f * d * d);
        float r  = __expf((25.0f / 49.0f) * d);
        float p  = e0;
        #pragma unroll
        for (int j = 0; j < NBINS; j++) {
            s_feat[tid * NBINS + j] = p * s_tc[j];
            p *= r;
        }
        // edge_index (as float32): [row, nbr] pairs
        size_t eo = (size_t)row * (2 * KNBR) + 2 * tid;
        out[eo]     = (float)row;
        out[eo + 1] = (float)s_i[tid];
    }
    __syncthreads();

    // ---- Phase 4: coalesced feature writeback ----
    float* __restrict__ outF = out + (size_t)N_ATOMS * KNBR * 2
                                   + (size_t)row * (KNBR * NBINS);
    #pragma unroll
    for (int i = tid; i < KNBR * NBINS; i += THREADS)
        outF[i] = s_feat[i];
}

extern "C" void kernel_launch(void* const* d_in, const int* in_sizes, int n_in,
                              void* d_out, int out_size)
{
    (void)in_sizes; (void)n_in; (void)out_size;
    const float* dm = (const float*)d_in[0];
    float* out = (float*)d_out;
    edge_featurizer_kernel<<<N_ATOMS, THREADS>>>(dm, out);
}

// round 2
// speedup vs baseline: 2.0487x; 2.0487x over previous
#include <cuda_runtime.h>
#include <stdint.h>

// EdgeFeaturizer: per-row 12 smallest of an 8192x8192 uniform distance matrix,
// then edge_index [n*k,2] + Gaussian RBF features [n*k,50].

#define N_ATOMS   8192
#define KNBR      12
#define NBINS     50
#define CAP       192           // candidate buffer per row (mean ~41 at t=0.005)
#define THREADS   256
#define T0        0.005f

__global__ __launch_bounds__(THREADS, 6)
void edge_featurizer_kernel(const float* __restrict__ dm, float* __restrict__ out)
{
    __shared__ unsigned long long cand[CAP];
    __shared__ int   s_count;
    __shared__ float s_tc[NBINS];        // exp(-12.5 * c_j^2)
    __shared__ float s_d[KNBR];
    __shared__ int   s_i[KNBR];
    __shared__ float s_feat[KNBR * NBINS];

    const int row = blockIdx.x;
    const int tid = threadIdx.x;
    const float4* __restrict__ rp =
        reinterpret_cast<const float4*>(dm + (size_t)row * N_ATOMS);

    if (tid < NBINS) {
        float c = (float)tid * (1.0f / 49.0f);
        s_tc[tid] = __expf(-12.5f * c * c);
    }
    if (tid == 0) s_count = 0;
    __syncthreads();

    // ---- Phase 1: exact threshold-compaction with fallback ----
    float t = T0;
    int   c;
    for (;;) {
        #pragma unroll
        for (int half = 0; half < 2; half++) {
            // batch-4 prefetch: 4 independent LDG.128 in flight per warp
            const int i0 = tid + (half * 4 + 0) * THREADS;
            const int i1 = tid + (half * 4 + 1) * THREADS;
            const int i2 = tid + (half * 4 + 2) * THREADS;
            const int i3 = tid + (half * 4 + 3) * THREADS;
            float4 v0 = __ldcs(rp + i0);
            float4 v1 = __ldcs(rp + i1);
            float4 v2 = __ldcs(rp + i2);
            float4 v3 = __ldcs(rp + i3);

            #pragma unroll
            for (int j = 0; j < 4; j++) {
                float4 v = (j == 0) ? v0 : (j == 1) ? v1 : (j == 2) ? v2 : v3;
                int    i = (j == 0) ? i0 : (j == 1) ? i1 : (j == 2) ? i2 : i3;
                float mn = fminf(fminf(v.x, v.y), fminf(v.z, v.w));
                unsigned bal = __ballot_sync(0xffffffffu, mn < t);
                if (bal) {                               // warp-uniform branch
                    int h = (v.x < t) + (v.y < t) + (v.z < t) + (v.w < t);
                    int p = 0;
                    if (h) p = atomicAdd(&s_count, h);
                    unsigned base = 4u * (unsigned)i;
                    if (v.x < t && p < CAP)
                        cand[p++] = (((unsigned long long)__float_as_uint(v.x)) << 32) | (base + 0u);
                    if (v.y < t && p < CAP)
                        cand[p++] = (((unsigned long long)__float_as_uint(v.y)) << 32) | (base + 1u);
                    if (v.z < t && p < CAP)
                        cand[p++] = (((unsigned long long)__float_as_uint(v.z)) << 32) | (base + 2u);
                    if (v.w < t && p < CAP)
                        cand[p++] = (((unsigned long long)__float_as_uint(v.w)) << 32) | (base + 3u);
                }
            }
        }
        __syncthreads();
        c = s_count;
        __syncthreads();                 // everyone has read c before reset
        if (c >= KNBR && c <= CAP) break;
        t = (c < KNBR) ? t * 8.0f : t * 0.25f;
        if (tid == 0) s_count = 0;
        __syncthreads();
    }

    // ---- Phase 2: warp 0, register-resident 12-smallest extraction ----
    if (tid < 32) {
        unsigned long long k[CAP / 32];          // 6 keys per lane
        #pragma unroll
        for (int j = 0; j < CAP / 32; j++) {
            int i = tid + j * 32;
            k[j] = (i < c) ? cand[i] : ~0ull;
        }
        #pragma unroll
        for (int s = 0; s < KNBR; s++) {
            unsigned long long best = k[0];
            #pragma unroll
            for (int j = 1; j < CAP / 32; j++) best = (k[j] < best) ? k[j] : best;
            #pragma unroll
            for (int off = 16; off > 0; off >>= 1) {
                unsigned long long o = __shfl_down_sync(0xffffffffu, best, off);
                best = (o < best) ? o : best;
            }
            best = __shfl_sync(0xffffffffu, best, 0);
            #pragma unroll
            for (int j = 0; j < CAP / 32; j++)       // keys unique (idx in key)
                if (k[j] == best) k[j] = ~0ull;
            if (tid == 0) {
                s_d[s] = __uint_as_float((unsigned)(best >> 32));
                s_i[s] = (int)(best & 0xffffffffu);
            }
        }
    }
    __syncthreads();

    // ---- Phase 3: features via geometric recurrence (2 MUFU per edge) ----
    // exp(-12.5 (d - c_j)^2) = exp(-12.5 d^2) * r^j * exp(-12.5 c_j^2),
    // r = exp(25 * d / 49).
    if (tid < KNBR) {
        float d  = s_d[tid];
        float e0 = __expf(-12.5f * d * d);
        float r  = __expf((25.0f / 49.0f) * d);
        float p  = e0;
        #pragma unroll
        for (int j = 0; j < NBINS; j++) {
            s_feat[tid * NBINS + j] = p * s_tc[j];
            p *= r;
        }
        size_t eo = (size_t)row * (2 * KNBR) + 2 * tid;
        out[eo]     = (float)row;
        out[eo + 1] = (float)s_i[tid];
    }
    __syncthreads();

    // ---- Phase 4: coalesced feature writeback ----
    float* __restrict__ outF = out + (size_t)N_ATOMS * KNBR * 2
                                   + (size_t)row * (KNBR * NBINS);
    #pragma unroll
    for (int i = tid; i < KNBR * NBINS; i += THREADS)
        outF[i] = s_feat[i];
}

extern "C" void kernel_launch(void* const* d_in, const int* in_sizes, int n_in,
                              void* d_out, int out_size)
{
    (void)in_sizes; (void)n_in; (void)out_size;
    const float* dm = (const float*)d_in[0];
    float* out = (float*)d_out;
    edge_featurizer_kernel<<<N_ATOMS, THREADS>>>(dm, out);
}

// round 3
// speedup vs baseline: 2.5820x; 1.2603x over previous
#include <cuda_runtime.h>
#include <stdint.h>

// EdgeFeaturizer: per-row 12 smallest of an 8192x8192 uniform distance matrix,
// then edge_index [n*k,2] + Gaussian RBF features [n*k,50].

#define N_ATOMS   8192
#define KNBR      12
#define NBINS     50
#define CAP       192           // candidate buffer per row (mean ~41 at t=0.005)
#define THREADS   256
#define T0        0.005f

__global__ __launch_bounds__(THREADS, 6)
void edge_featurizer_kernel(const float* __restrict__ dm, float* __restrict__ out)
{
    __shared__ unsigned long long cand[CAP];
    __shared__ int   s_count;
    __shared__ float s_tc[NBINS];        // exp(-12.5 * c_j^2)
    __shared__ float s_d[KNBR];
    __shared__ int   s_i[KNBR];
    __shared__ float s_feat[KNBR * NBINS];

    const int row = blockIdx.x;
    const int tid = threadIdx.x;
    const float4* __restrict__ rp =
        reinterpret_cast<const float4*>(dm + (size_t)row * N_ATOMS);

    if (tid < NBINS) {
        float c = (float)tid * (1.0f / 49.0f);
        s_tc[tid] = __expf(-12.5f * c * c);
    }
    if (tid == 0) s_count = 0;
    __syncthreads();

    // ---- Phase 1: exact threshold-compaction with fallback ----
    float t = T0;
    int   c;
    for (;;) {
        #pragma unroll
        for (int half = 0; half < 2; half++) {
            const int i0 = tid + (half * 4 + 0) * THREADS;
            const int i1 = tid + (half * 4 + 1) * THREADS;
            const int i2 = tid + (half * 4 + 2) * THREADS;
            const int i3 = tid + (half * 4 + 3) * THREADS;
            // 4 independent LDG.128 in flight per thread
            float4 v0 = __ldcs(rp + i0);
            float4 v1 = __ldcs(rp + i1);
            float4 v2 = __ldcs(rp + i2);
            float4 v3 = __ldcs(rp + i3);

            // one threshold test per 16 elements (hit prob ~7.7%/thread)
            float m0 = fminf(fminf(v0.x, v0.y), fminf(v0.z, v0.w));
            float m1 = fminf(fminf(v1.x, v1.y), fminf(v1.z, v1.w));
            float m2 = fminf(fminf(v2.x, v2.y), fminf(v2.z, v2.w));
            float m3 = fminf(fminf(v3.x, v3.y), fminf(v3.z, v3.w));
            float mn = fminf(fminf(m0, m1), fminf(m2, m3));
            if (mn < t) {                         // rare body
                #pragma unroll
                for (int j = 0; j < 4; j++) {
                    float4 v = (j == 0) ? v0 : (j == 1) ? v1 : (j == 2) ? v2 : v3;
                    int    i = (j == 0) ? i0 : (j == 1) ? i1 : (j == 2) ? i2 : i3;
                    int h = (v.x < t) + (v.y < t) + (v.z < t) + (v.w < t);
                    if (h) {
                        int p = atomicAdd(&s_count, h);
                        unsigned base = 4u * (unsigned)i;
                        if (v.x < t && p < CAP)
                            cand[p++] = (((unsigned long long)__float_as_uint(v.x)) << 32) | (base + 0u);
                        if (v.y < t && p < CAP)
                            cand[p++] = (((unsigned long long)__float_as_uint(v.y)) << 32) | (base + 1u);
                        if (v.z < t && p < CAP)
                            cand[p++] = (((unsigned long long)__float_as_uint(v.z)) << 32) | (base + 2u);
                        if (v.w < t && p < CAP)
                            cand[p++] = (((unsigned long long)__float_as_uint(v.w)) << 32) | (base + 3u);
                    }
                }
            }
        }
        __syncthreads();
        c = s_count;
        __syncthreads();                 // everyone has read c before reset
        if (c >= KNBR && c <= CAP) break;
        t = (c < KNBR) ? t * 8.0f : t * 0.25f;
        if (tid == 0) s_count = 0;
        __syncthreads();
    }

    // ---- Phase 2: parallel rank selection (keys unique -> ranks distinct) ----
    if (tid < c) {
        unsigned long long mine = cand[tid];
        int rank = 0;
        int j = 0;
        for (; j + 4 <= c; j += 4) {
            rank += (cand[j + 0] < mine);
            rank += (cand[j + 1] < mine);
            rank += (cand[j + 2] < mine);
            rank += (cand[j + 3] < mine);
        }
        for (; j < c; j++) rank += (cand[j] < mine);
        if (rank < KNBR) {
            s_d[rank] = __uint_as_float((unsigned)(mine >> 32));
            s_i[rank] = (int)(mine & 0xffffffffu);
        }
    }
    __syncthreads();

    // ---- Phase 3: features via geometric recurrence (2 MUFU per edge) ----
    // exp(-12.5 (d - c_j)^2) = exp(-12.5 d^2) * r^j * exp(-12.5 c_j^2),
    // r = exp(25 * d / 49).
    if (tid < KNBR) {
        float d  = s_d[tid];
        float e0 = __expf(-12.5f * d * d);
        float r  = __expf((25.0f / 49.0f) * d);
        float p  = e0;
        #pragma unroll
        for (int j = 0; j < NBINS; j++) {
            s_feat[tid * NBINS + j] = p * s_tc[j];
            p *= r;
        }
        size_t eo = (size_t)row * (2 * KNBR) + 2 * tid;
        out[eo]     = (float)row;
        out[eo + 1] = (float)s_i[tid];
    }
    __syncthreads();

    // ---- Phase 4: coalesced feature writeback ----
    float* __restrict__ outF = out + (size_t)N_ATOMS * KNBR * 2
                                   + (size_t)row * (KNBR * NBINS);
    #pragma unroll
    for (int i = tid; i < KNBR * NBINS; i += THREADS)
        outF[i] = s_feat[i];
}

extern "C" void kernel_launch(void* const* d_in, const int* in_sizes, int n_in,
                              void* d_out, int out_size)
{
    (void)in_sizes; (void)n_in; (void)out_size;
    const float* dm = (const float*)d_in[0];
    float* out = (float*)d_out;
    edge_featurizer_kernel<<<N_ATOMS, THREADS>>>(dm, out);
}